// round 13
// baseline (speedup 1.0000x reference)
#include <cuda_runtime.h>
#include <cuda_fp16.h>
#include <stdint.h>

#define TOKENS 256
#define IN_F   4096
#define OUT_F  11008
#define RANK   16
#define SCALINGF 2.0f

#define BM 128
#define BN 64
#define BK 64
#define THREADS 128
#define K_ITERS (IN_F / BK)   // 64

// per-stage byte offsets (stage base 1024-aligned):
//   x fp16 tile 16KB | W fp16 tile 8KB | raw q codes 16KB
#define XH_OFF 0
#define WH_OFF 16384
#define QC_OFF 24576
#define STAGE_BYTES 40960
#define SMEM_DYN (2 * STAGE_BYTES + 1024)

__constant__ float c_nf4[16] = {
    -1.0f, -0.6961928009986877f, -0.5250730514526367f, -0.39491748809814453f,
    -0.28444138169288635f, -0.18477343022823334f, -0.09105003625154495f, 0.0f,
    0.07958029955625534f, 0.16093020141124725f, 0.24611230194568634f,
    0.33791524171829224f, 0.44070982933044434f, 0.5626170039176941f,
    0.7229568362236023f, 1.0f
};

__device__ float g_u[TOKENS * RANK];
__device__ __align__(16) __half g_xh[TOKENS * IN_F];

// ------------------------------------------------------------------ helpers
__device__ __forceinline__ uint32_t smem_u32(const void* p) {
    uint32_t a;
    asm("{ .reg .u64 t; cvta.to.shared.u64 t, %1; cvt.u32.u64 %0, t; }"
        : "=r"(a) : "l"(p));
    return a;
}

__device__ __forceinline__ uint32_t sw128(uint32_t o) {
    return o ^ ((o >> 3) & 0x70);
}

__device__ __forceinline__ void cp16(uint32_t dst, const void* src) {
    asm volatile("cp.async.cg.shared.global [%0], [%1], 16;"
                 :: "r"(dst), "l"(src) : "memory");
}
__device__ __forceinline__ void cp_commit() {
    asm volatile("cp.async.commit_group;" ::: "memory");
}
__device__ __forceinline__ void cp_wait0() {
    asm volatile("cp.async.wait_group 0;" ::: "memory");
}

__device__ __forceinline__ void ldsm4(uint32_t* r, uint32_t addr) {
    asm volatile("ldmatrix.sync.aligned.m8n8.x4.shared.b16 {%0,%1,%2,%3}, [%4];"
                 : "=r"(r[0]), "=r"(r[1]), "=r"(r[2]), "=r"(r[3]) : "r"(addr));
}

__device__ __forceinline__ void mma16816(float* c, const uint32_t* a,
                                         const uint32_t* b) {
    asm volatile(
        "mma.sync.aligned.m16n8k16.row.col.f32.f16.f16.f32 "
        "{%0,%1,%2,%3},{%4,%5,%6,%7},{%8,%9},{%0,%1,%2,%3};"
        : "+f"(c[0]), "+f"(c[1]), "+f"(c[2]), "+f"(c[3])
        : "r"(a[0]), "r"(a[1]), "r"(a[2]), "r"(a[3]), "r"(b[0]), "r"(b[1]));
}

__device__ __forceinline__ uint32_t pack_f16x2(float a, float b) {
    uint32_t d;
    asm("cvt.rn.f16x2.f32 %0, %1, %2;" : "=r"(d) : "f"(b), "f"(a));
    return d;
}

__device__ __forceinline__ int4 lds128_int4(uint32_t addr) {
    int4 v;
    asm volatile("ld.shared.v4.b32 {%0,%1,%2,%3}, [%4];"
                 : "=r"(v.x), "=r"(v.y), "=r"(v.z), "=r"(v.w) : "r"(addr));
    return v;
}

__device__ __forceinline__ float dot16(const float* a, const float* b) {
    float s = 0.0f;
#pragma unroll
    for (int v = 0; v < 4; ++v) {
        float4 x = ((const float4*)a)[v];
        float4 y = ((const float4*)b)[v];
        s += x.x * y.x + x.y * y.y + x.z * y.z + x.w * y.w;
    }
    return s;
}

// ------------------------------------------------------------------ prep 1: x -> fp16
__global__ __launch_bounds__(256)
void convert_kernel(const float* __restrict__ x) {
    const int i = blockIdx.x * 256 + threadIdx.x;
    const float4* xs = (const float4*)x;
    uint2* xd = (uint2*)g_xh;
#pragma unroll
    for (int c = 0; c < 4; ++c) {
        int idx = i + c * 65536;
        float4 v = xs[idx];
        uint2 h;
        h.x = pack_f16x2(v.x, v.y);
        h.y = pack_f16x2(v.z, v.w);
        xd[idx] = h;
    }
}

// ------------------------------------------------------------------ prep 2: u = 2 * x @ A^T
__global__ __launch_bounds__(256)
void u_kernel(const float* __restrict__ x, const float* __restrict__ A) {
    const int gw = blockIdx.x * 8 + (threadIdx.x >> 5);
    const int lane = threadIdx.x & 31;
    const int t = gw >> 4;
    const int r = gw & 15;

    const float4* xr = (const float4*)(x + (size_t)t * IN_F);
    const float4* Ar = (const float4*)(A + (size_t)r * IN_F);
    float s = 0.0f;
#pragma unroll 8
    for (int kk = 0; kk < 32; ++kk) {
        float4 xv = xr[kk * 32 + lane];
        float4 av = Ar[kk * 32 + lane];
        s += xv.x * av.x + xv.y * av.y + xv.z * av.z + xv.w * av.w;
    }
#pragma unroll
    for (int off = 16; off > 0; off >>= 1)
        s += __shfl_xor_sync(0xFFFFFFFFu, s, off);
    if (lane == 0) g_u[t * RANK + r] = s * SCALINGF;
}

// ------------------------------------------------------------------ main
extern __shared__ char dynsmem[];

__global__ __launch_bounds__(THREADS, 2)
void lora4bit_fp16_kernel(const int* __restrict__ q,
                          const float* __restrict__ absmax,
                          const float* __restrict__ lora_B,
                          float* __restrict__ out) {
    __shared__ float lut[16];
    __shared__ float Us[BM * RANK];
    __shared__ float Bs[BN * RANK];

    const int tid  = threadIdx.x;
    const int wid  = tid >> 5;
    const int lane = tid & 31;
    const int bn = blockIdx.x * BN;
    const int bm = blockIdx.y * BM;

    const uint32_t dbase = (smem_u32(dynsmem) + 1023u) & ~1023u;
    char* dptr = dynsmem + (dbase - smem_u32(dynsmem));

    if (tid < 16) lut[tid] = c_nf4[tid];
    {
        const float4* src = (const float4*)(g_u + (size_t)bm * RANK);
#pragma unroll
        for (int k = 0; k < 4; ++k)
            ((float4*)Us)[tid + k * 128] = src[tid + k * 128];
    }
    {
        const float4* src = (const float4*)(lora_B + (size_t)bn * RANK);
#pragma unroll
        for (int k = 0; k < 2; ++k)
            ((float4*)Bs)[tid + k * 128] = src[tid + k * 128];
    }

    // ---- producer index mapping
    const int nrow  = tid >> 1;           // W tile row (n), 0..63
    const int khalf = (tid & 1) * 32;     // 32 codes each
    const int xrow  = tid >> 3;           // x rows 0..15 (+16*g)
    const int xch   = tid & 7;            // 16B chunk in 128B row
    const int csw   = tid & 7;            // code-chunk xor swizzle key

    const int*   qptr  = q + (size_t)(bn + nrow) * IN_F + khalf;
    const float* amptr = absmax + (size_t)(bn + nrow) * (IN_F / 64);
    const __half* xptr = g_xh + (size_t)bm * IN_F;

    // per-thread private code region in stage: tid*128 .. +128
    const uint32_t qc_self = dbase + QC_OFF + (uint32_t)tid * 128;

    // ---- prologue: issue cp.async for iter 0 (x + codes)
    {
#pragma unroll
        for (int g = 0; g < 8; ++g) {
            int row = xrow + g * 16;
            uint32_t off = sw128((uint32_t)(row * 128 + xch * 16));
            cp16(dbase + XH_OFF + off, xptr + (size_t)row * IN_F + xch * 8);
        }
#pragma unroll
        for (int c = 0; c < 8; ++c)
            cp16(qc_self + ((uint32_t)(c ^ csw)) * 16, qptr + c * 4);
        cp_commit();
    }
    float scale_cur = amptr[0];
    __syncthreads();   // lut/Us/Bs visible

    // ---- mma lane mapping (warp tile 64x32, warps 2x2)
    const int wm = (wid & 1) * 64;
    const int wn = (wid >> 1) * 32;
    const int am_r = (lane & 7) + ((lane >> 3) & 1) * 8;
    const int a_kb = (lane >> 4) * 16;
    const int b_nr = (lane & 7) + ((lane >> 4) & 1) * 8;
    const int b_kb = ((lane >> 3) & 1) * 16;

    float acc[4][4][4];
#pragma unroll
    for (int i = 0; i < 4; ++i)
#pragma unroll
        for (int j = 0; j < 4; ++j)
#pragma unroll
            for (int e = 0; e < 4; ++e) acc[i][j][e] = 0.0f;

    for (int it = 0; it < K_ITERS; ++it) {
        const int s = it & 1;
        const uint32_t stg = dbase + s * STAGE_BYTES;
        char* stgp = dptr + s * STAGE_BYTES;

        cp_wait0();   // x + codes of stage s arrived (this thread's own copies)

        // ---- dequant: read own codes from smem, write W fp16 tile
        {
            const uint32_t qc_s = qc_self + (uint32_t)s * STAGE_BYTES;
            int4 qreg[8];
#pragma unroll
            for (int c = 0; c < 8; ++c)
                qreg[c] = lds128_int4(qc_s + ((uint32_t)(c ^ csw)) * 16);

            float s0 = scale_cur;
#pragma unroll
            for (int g = 0; g < 4; ++g) {
                uint4 hib;
                uint32_t* hp = &hib.x;
#pragma unroll
                for (int p = 0; p < 2; ++p) {
                    int4 qq = qreg[g * 2 + p];
                    hp[p * 2 + 0] = pack_f16x2(lut[qq.x & 15] * s0,
                                               lut[qq.y & 15] * s0);
                    hp[p * 2 + 1] = pack_f16x2(lut[qq.z & 15] * s0,
                                               lut[qq.w & 15] * s0);
                }
                uint32_t off =
                    sw128((uint32_t)(nrow * 128 + khalf * 2 + g * 16));
                *(uint4*)(stgp + WH_OFF + off) = hib;
            }
        }
        __syncthreads();   // W(s) visible to all; stage s^1 fully consumed

        // ---- issue cp.async for iter it+1 into stage s^1; prefetch scale
        if (it + 1 < K_ITERS) {
            const uint32_t ost = dbase + (s ^ 1) * STAGE_BYTES;
            const int kk = (it + 1) * BK;
            const __half* xs = xptr + kk + xch * 8;
#pragma unroll
            for (int g = 0; g < 8; ++g) {
                int row = xrow + g * 16;
                uint32_t off = sw128((uint32_t)(row * 128 + xch * 16));
                cp16(ost + XH_OFF + off, xs + (size_t)row * IN_F);
            }
            const int* qs = qptr + kk;
            const uint32_t qc_o = qc_self + (uint32_t)(s ^ 1) * STAGE_BYTES;
#pragma unroll
            for (int c = 0; c < 8; ++c)
                cp16(qc_o + ((uint32_t)(c ^ csw)) * 16, qs + c * 4);
            cp_commit();

            scale_cur = amptr[it + 1];
        }

        // ---- compute on stage s
#pragma unroll
        for (int ks = 0; ks < 4; ++ks) {
            uint32_t ah[4][4];
#pragma unroll
            for (int mi = 0; mi < 4; ++mi) {
                uint32_t off = sw128(
                    (uint32_t)((wm + mi * 16 + am_r) * 128 + ks * 32 + a_kb));
                ldsm4(ah[mi], stg + XH_OFF + off);
            }
            uint32_t bh[4][2];
#pragma unroll
            for (int jp = 0; jp < 2; ++jp) {
                uint32_t off = sw128(
                    (uint32_t)((wn + jp * 16 + b_nr) * 128 + ks * 32 + b_kb));
                uint32_t t[4];
                ldsm4(t, stg + WH_OFF + off);
                bh[jp * 2][0] = t[0]; bh[jp * 2][1] = t[1];
                bh[jp * 2 + 1][0] = t[2]; bh[jp * 2 + 1][1] = t[3];
            }
#pragma unroll
            for (int mi = 0; mi < 4; ++mi)
#pragma unroll
                for (int nj = 0; nj < 4; ++nj)
                    mma16816(acc[mi][nj], ah[mi], bh[nj]);
        }
    }

    // ---- epilogue: LoRA add + store
#pragma unroll
    for (int mi = 0; mi < 4; ++mi) {
        const int rloc0 = wm + mi * 16 + (lane >> 2);
        const int rloc1 = rloc0 + 8;
        const float* u0 = Us + rloc0 * RANK;
        const float* u1 = Us + rloc1 * RANK;
#pragma unroll
        for (int nj = 0; nj < 4; ++nj) {
            const int c0 = wn + nj * 8 + (lane & 3) * 2;
            const float* bc0 = Bs + c0 * RANK;
            const float* bc1 = bc0 + RANK;
            float2 v0, v1;
            v0.x = acc[mi][nj][0] + dot16(u0, bc0);
            v0.y = acc[mi][nj][1] + dot16(u0, bc1);
            v1.x = acc[mi][nj][2] + dot16(u1, bc0);
            v1.y = acc[mi][nj][3] + dot16(u1, bc1);
            *(float2*)(out + (size_t)(bm + rloc0) * OUT_F + bn + c0) = v0;
            *(float2*)(out + (size_t)(bm + rloc1) * OUT_F + bn + c0) = v1;
        }
    }
}

// ------------------------------------------------------------------ launch
extern "C" void kernel_launch(void* const* d_in, const int* in_sizes, int n_in,
                              void* d_out, int out_size) {
    const float* x      = (const float*)d_in[0];
    const int*   q      = (const int*)  d_in[1];
    const float* absmax = (const float*)d_in[2];
    const float* lora_A = (const float*)d_in[3];
    const float* lora_B = (const float*)d_in[4];
    float* out = (float*)d_out;

    cudaFuncSetAttribute(lora4bit_fp16_kernel,
                         cudaFuncAttributeMaxDynamicSharedMemorySize, SMEM_DYN);

    convert_kernel<<<256, 256>>>(x);
    u_kernel<<<512, 256>>>(x, lora_A);

    dim3 grid(OUT_F / BN, TOKENS / BM);   // (172, 2) = 344
    lora4bit_fp16_kernel<<<grid, THREADS, SMEM_DYN>>>(q, absmax, lora_B, out);
}

// round 14
// speedup vs baseline: 1.3057x; 1.3057x over previous
#include <cuda_runtime.h>
#include <cuda_fp16.h>
#include <stdint.h>

#define TOKENS 256
#define IN_F   4096
#define OUT_F  11008
#define RANK   16
#define SCALINGF 2.0f

#define BM 128
#define BN 64
#define BK 64
#define THREADS 128
#define K_ITERS (IN_F / BK)   // 64

// per-stage byte offsets (stage base 1024-aligned): x 16KB + w 8KB
#define XH_OFF 0
#define WH_OFF 16384
#define STAGE_BYTES 24576
#define SMEM_DYN (2 * STAGE_BYTES + 1024)

__constant__ float c_nf4[16] = {
    -1.0f, -0.6961928009986877f, -0.5250730514526367f, -0.39491748809814453f,
    -0.28444138169288635f, -0.18477343022823334f, -0.09105003625154495f, 0.0f,
    0.07958029955625534f, 0.16093020141124725f, 0.24611230194568634f,
    0.33791524171829224f, 0.44070982933044434f, 0.5626170039176941f,
    0.7229568362236023f, 1.0f
};

__device__ float g_u[TOKENS * RANK];
__device__ __align__(16) __half g_xh[TOKENS * IN_F];

// ------------------------------------------------------------------ helpers
__device__ __forceinline__ uint32_t smem_u32(const void* p) {
    uint32_t a;
    asm("{ .reg .u64 t; cvta.to.shared.u64 t, %1; cvt.u32.u64 %0, t; }"
        : "=r"(a) : "l"(p));
    return a;
}

__device__ __forceinline__ uint32_t sw128(uint32_t o) {
    return o ^ ((o >> 3) & 0x70);
}

__device__ __forceinline__ void cp16(uint32_t dst, const void* src) {
    asm volatile("cp.async.cg.shared.global [%0], [%1], 16;"
                 :: "r"(dst), "l"(src) : "memory");
}
__device__ __forceinline__ void cp_commit() {
    asm volatile("cp.async.commit_group;" ::: "memory");
}
__device__ __forceinline__ void cp_wait0() {
    asm volatile("cp.async.wait_group 0;" ::: "memory");
}

__device__ __forceinline__ void ldsm4(uint32_t* r, uint32_t addr) {
    asm volatile("ldmatrix.sync.aligned.m8n8.x4.shared.b16 {%0,%1,%2,%3}, [%4];"
                 : "=r"(r[0]), "=r"(r[1]), "=r"(r[2]), "=r"(r[3]) : "r"(addr));
}

__device__ __forceinline__ void mma16816(float* c, const uint32_t* a,
                                         const uint32_t* b) {
    asm volatile(
        "mma.sync.aligned.m16n8k16.row.col.f32.f16.f16.f32 "
        "{%0,%1,%2,%3},{%4,%5,%6,%7},{%8,%9},{%0,%1,%2,%3};"
        : "+f"(c[0]), "+f"(c[1]), "+f"(c[2]), "+f"(c[3])
        : "r"(a[0]), "r"(a[1]), "r"(a[2]), "r"(a[3]), "r"(b[0]), "r"(b[1]));
}

__device__ __forceinline__ uint32_t pack_f16x2(float a, float b) {
    uint32_t d;
    asm("cvt.rn.f16x2.f32 %0, %1, %2;" : "=r"(d) : "f"(b), "f"(a));
    return d;
}

__device__ __forceinline__ float dot16(const float* a, const float* b) {
    float s = 0.0f;
#pragma unroll
    for (int v = 0; v < 4; ++v) {
        float4 x = ((const float4*)a)[v];
        float4 y = ((const float4*)b)[v];
        s += x.x * y.x + x.y * y.y + x.z * y.z + x.w * y.w;
    }
    return s;
}

// ------------------------------------------------------------------ prep 1: x -> fp16
__global__ __launch_bounds__(256)
void convert_kernel(const float* __restrict__ x) {
    const int i = blockIdx.x * 256 + threadIdx.x;
    const float4* xs = (const float4*)x;
    uint2* xd = (uint2*)g_xh;
#pragma unroll
    for (int c = 0; c < 4; ++c) {
        int idx = i + c * 65536;
        float4 v = xs[idx];
        uint2 h;
        h.x = pack_f16x2(v.x, v.y);
        h.y = pack_f16x2(v.z, v.w);
        xd[idx] = h;
    }
}

// ------------------------------------------------------------------ prep 2: u = 2 * x @ A^T
__global__ __launch_bounds__(256)
void u_kernel(const float* __restrict__ x, const float* __restrict__ A) {
    const int gw = blockIdx.x * 8 + (threadIdx.x >> 5);
    const int lane = threadIdx.x & 31;
    const int t = gw >> 4;
    const int r = gw & 15;

    const float4* xr = (const float4*)(x + (size_t)t * IN_F);
    const float4* Ar = (const float4*)(A + (size_t)r * IN_F);
    float s = 0.0f;
#pragma unroll 8
    for (int kk = 0; kk < 32; ++kk) {
        float4 xv = xr[kk * 32 + lane];
        float4 av = Ar[kk * 32 + lane];
        s += xv.x * av.x + xv.y * av.y + xv.z * av.z + xv.w * av.w;
    }
#pragma unroll
    for (int off = 16; off > 0; off >>= 1)
        s += __shfl_xor_sync(0xFFFFFFFFu, s, off);
    if (lane == 0) g_u[t * RANK + r] = s * SCALINGF;
}

// ------------------------------------------------------------------ main
extern __shared__ char dynsmem[];

__global__ __launch_bounds__(THREADS, 3)
void lora4bit_fp16_kernel(const int* __restrict__ q,
                          const float* __restrict__ absmax,
                          const float* __restrict__ lora_B,
                          float* __restrict__ out) {
    __shared__ float lut[16];
    __shared__ float Us[BM * RANK];
    __shared__ float Bs[BN * RANK];

    const int tid  = threadIdx.x;
    const int wid  = tid >> 5;
    const int lane = tid & 31;
    const int bn = blockIdx.x * BN;
    const int bm = blockIdx.y * BM;

    const uint32_t dbase = (smem_u32(dynsmem) + 1023u) & ~1023u;
    char* dptr = dynsmem + (dbase - smem_u32(dynsmem));

    if (tid < 16) lut[tid] = c_nf4[tid];
    {
        const float4* src = (const float4*)(g_u + (size_t)bm * RANK);
#pragma unroll
        for (int k = 0; k < 4; ++k)
            ((float4*)Us)[tid + k * 128] = src[tid + k * 128];
    }
    {
        const float4* src = (const float4*)(lora_B + (size_t)bn * RANK);
#pragma unroll
        for (int k = 0; k < 2; ++k)
            ((float4*)Bs)[tid + k * 128] = src[tid + k * 128];
    }

    // ---- producer index mapping
    const int nrow  = tid >> 1;           // W tile row (n), 0..63
    const int khalf = (tid & 1) * 32;     // 32 codes each
    const int xrow  = tid >> 3;           // x rows 0..15 (+16*g)
    const int xch   = tid & 7;            // 16B chunk in 128B row

    const int*   qptr  = q + (size_t)(bn + nrow) * IN_F + khalf;
    const float* amptr = absmax + (size_t)(bn + nrow) * (IN_F / 64);
    const __half* xptr = g_xh + (size_t)bm * IN_F;

    // ---- prologue: codes for it=0, cp.async x stage 0
    int4 qreg[8];
    {
        const int4* p = (const int4*)qptr;
#pragma unroll
        for (int v = 0; v < 8; ++v) qreg[v] = p[v];
    }
    float scale_cur = amptr[0];

    {
#pragma unroll
        for (int g = 0; g < 8; ++g) {
            int row = xrow + g * 16;
            uint32_t off = sw128((uint32_t)(row * 128 + xch * 16));
            cp16(dbase + XH_OFF + off, xptr + (size_t)row * IN_F + xch * 8);
        }
        cp_commit();
    }
    __syncthreads();   // lut/Us/Bs visible

    // ---- mma lane mapping (warp tile 64x32, warps 2x2)
    const int wm = (wid & 1) * 64;
    const int wn = (wid >> 1) * 32;
    const int am_r = (lane & 7) + ((lane >> 3) & 1) * 8;
    const int a_kb = (lane >> 4) * 16;
    const int b_nr = (lane & 7) + ((lane >> 4) & 1) * 8;
    const int b_kb = ((lane >> 3) & 1) * 16;

    float acc[4][4][4];
#pragma unroll
    for (int i = 0; i < 4; ++i)
#pragma unroll
        for (int j = 0; j < 4; ++j)
#pragma unroll
            for (int e = 0; e < 4; ++e) acc[i][j][e] = 0.0f;

    for (int it = 0; it < K_ITERS; ++it) {
        const int s = it & 1;
        const uint32_t stg = dbase + s * STAGE_BYTES;
        char* stgp = dptr + s * STAGE_BYTES;

        // ---- dequant W chunk (registers only) BEFORE waiting on cp.async,
        //      so the x-tile wait overlaps with dequant ALU.
        uint4 wh[4];
        {
            float s0 = scale_cur;
#pragma unroll
            for (int g = 0; g < 4; ++g) {
                uint32_t* hp = &wh[g].x;
#pragma unroll
                for (int p = 0; p < 2; ++p) {
                    int4 qq = qreg[g * 2 + p];
                    hp[p * 2 + 0] = pack_f16x2(lut[qq.x & 15] * s0,
                                               lut[qq.y & 15] * s0);
                    hp[p * 2 + 1] = pack_f16x2(lut[qq.z & 15] * s0,
                                               lut[qq.w & 15] * s0);
                }
            }
        }

        cp_wait0();   // x tile of stage s arrived

#pragma unroll
        for (int g = 0; g < 4; ++g) {
            uint32_t off = sw128((uint32_t)(nrow * 128 + khalf * 2 + g * 16));
            *(uint4*)(stgp + WH_OFF + off) = wh[g];
        }
        __syncthreads();   // W writes visible; stage s^1 consumers done

        // ---- prefetch next chunk: codes->regs, x->stage s^1
        if (it + 1 < K_ITERS) {
            const int4* p = (const int4*)(qptr + (it + 1) * BK);
#pragma unroll
            for (int v = 0; v < 8; ++v) qreg[v] = p[v];
            scale_cur = amptr[it + 1];

            uint32_t st = dbase + (s ^ 1) * STAGE_BYTES;
            const __half* xs = xptr + (it + 1) * BK + xch * 8;
#pragma unroll
            for (int g = 0; g < 8; ++g) {
                int row = xrow + g * 16;
                uint32_t off = sw128((uint32_t)(row * 128 + xch * 16));
                cp16(st + XH_OFF + off, xs + (size_t)row * IN_F);
            }
            cp_commit();
        }

        // ---- compute on stage s
#pragma unroll
        for (int ks = 0; ks < 4; ++ks) {
            uint32_t ah[4][4];
#pragma unroll
            for (int mi = 0; mi < 4; ++mi) {
                uint32_t off = sw128(
                    (uint32_t)((wm + mi * 16 + am_r) * 128 + ks * 32 + a_kb));
                ldsm4(ah[mi], stg + XH_OFF + off);
            }
            uint32_t bh[4][2];
#pragma unroll
            for (int jp = 0; jp < 2; ++jp) {
                uint32_t off = sw128(
                    (uint32_t)((wn + jp * 16 + b_nr) * 128 + ks * 32 + b_kb));
                uint32_t t[4];
                ldsm4(t, stg + WH_OFF + off);
                bh[jp * 2][0] = t[0]; bh[jp * 2][1] = t[1];
                bh[jp * 2 + 1][0] = t[2]; bh[jp * 2 + 1][1] = t[3];
            }
#pragma unroll
            for (int mi = 0; mi < 4; ++mi)
#pragma unroll
                for (int nj = 0; nj < 4; ++nj)
                    mma16816(acc[mi][nj], ah[mi], bh[nj]);
        }
    }

    // ---- epilogue: LoRA add + store
#pragma unroll
    for (int mi = 0; mi < 4; ++mi) {
        const int rloc0 = wm + mi * 16 + (lane >> 2);
        const int rloc1 = rloc0 + 8;
        const float* u0 = Us + rloc0 * RANK;
        const float* u1 = Us + rloc1 * RANK;
#pragma unroll
        for (int nj = 0; nj < 4; ++nj) {
            const int c0 = wn + nj * 8 + (lane & 3) * 2;
            const float* bc0 = Bs + c0 * RANK;
            const float* bc1 = bc0 + RANK;
            float2 v0, v1;
            v0.x = acc[mi][nj][0] + dot16(u0, bc0);
            v0.y = acc[mi][nj][1] + dot16(u0, bc1);
            v1.x = acc[mi][nj][2] + dot16(u1, bc0);
            v1.y = acc[mi][nj][3] + dot16(u1, bc1);
            *(float2*)(out + (size_t)(bm + rloc0) * OUT_F + bn + c0) = v0;
            *(float2*)(out + (size_t)(bm + rloc1) * OUT_F + bn + c0) = v1;
        }
    }
}

// ------------------------------------------------------------------ launch
extern "C" void kernel_launch(void* const* d_in, const int* in_sizes, int n_in,
                              void* d_out, int out_size) {
    const float* x      = (const float*)d_in[0];
    const int*   q      = (const int*)  d_in[1];
    const float* absmax = (const float*)d_in[2];
    const float* lora_A = (const float*)d_in[3];
    const float* lora_B = (const float*)d_in[4];
    float* out = (float*)d_out;

    cudaFuncSetAttribute(lora4bit_fp16_kernel,
                         cudaFuncAttributeMaxDynamicSharedMemorySize, SMEM_DYN);

    convert_kernel<<<256, 256>>>(x);
    u_kernel<<<512, 256>>>(x, lora_A);

    dim3 grid(OUT_F / BN, TOKENS / BM);   // (172, 2)
    lora4bit_fp16_kernel<<<grid, THREADS, SMEM_DYN>>>(q, absmax, lora_B, out);
}